// round 16
// baseline (speedup 1.0000x reference)
#include <cuda_runtime.h>
#include <cuda_fp16.h>
#include <math.h>
#include <cstdint>

// ---------------- problem constants ----------------
#define Bb   8
#define Tt   12
#define Vv   512
#define Cc   128
#define TSZ  3
#define LL   3
#define PP   12
#define BETA 2
#define TPAD (Tt + BETA)   // 14
#define C2   256
#define KV   (TSZ * Vv)    // 1536
#define KTC  (Tt * Cc)     // 1536
#define BT   (Bb * Tt)     // 96
#define KSPL 6             // gfs split-K
#define QSPL 4             // out split-q
#define ASPL 2             // agg split-K

#define PADH 72                             // halves per smem row (36 words), K=64 chunks
#define PADW (PADH / 2)                     // 36 words
#define TILE_WORDS (128 * PADW)             // 4608
#define TILE_BYTES (TILE_WORDS * 4)         // 18432
#define SMEM_PIPE  (4 * TILE_BYTES)         // 73728 (2 stages x A,B)

// ---------------- device scratch (static; no runtime alloc) ----------------
__device__ __align__(16) __half g_ht [Bb * TPAD * Vv * Cc];   // fp16 h [b][tp][v][c]
__device__ __align__(16) __half g_hTt[Bb * TPAD * Cc * Vv];   // fp16 h [b][tp][c][v]
__device__ __align__(16) __half g_Et [LL * Vv * KV];          // fp16 E
__device__ __align__(16) float  g_aggp[ASPL * BT * Vv * Cc];  // fp32 agg partials
__device__ __align__(16) float  g_z[BT * Vv * C2];
__device__ __align__(16) __half g_spart[KSPL * Bb * Vv * Cc]; // fp16 gfs partials
__device__ __align__(16) __half g_skipTt[Bb * Vv * 512];      // fp16 [b][v][o]
__device__ __align__(16) float  g_g[Bb * 1024 * Vv];
__device__ __align__(16) float  g_sep[LL * Vv * C2];
__device__ __align__(16) float  g_tep[LL * BT * C2];
__device__ __align__(16) __half g_xwTt[LL * C2 * Cc];         // fp16 [l][n][k]
__device__ __align__(16) __half g_fwt[4 * Cc * KTC];          // fp16 [s][o][tc]
__device__ __align__(16) __half g_gwt[1024 * 512];            // fp16 glu_w
__device__ __align__(16) float  g_gluwT[4 * Cc * C2];         // fp32 GFS GLU w, [s][c][o]
__device__ __align__(16) float  g_opart[QSPL * Bb * PP * Vv];

__device__ __forceinline__ float sigm(float x) { return 1.f / (1.f + expf(-x)); }
__device__ __forceinline__ uint32_t pack2(float lo, float hi) {
    __half2 h = __floats2half2_rn(lo, hi);
    return *reinterpret_cast<uint32_t*>(&h);
}
__device__ __forceinline__ uint32_t smem_u32(const void* p) {
    uint32_t a;
    asm("{ .reg .u64 t; cvta.to.shared.u64 t, %1; cvt.u32.u64 %0, t; }" : "=r"(a) : "l"(p));
    return a;
}
__device__ __forceinline__ void cpa16(uint32_t dst, const void* src) {
    asm volatile("cp.async.cg.shared.global [%0], [%1], 16;" :: "r"(dst), "l"(src));
}
#define CP_COMMIT() asm volatile("cp.async.commit_group;" ::: "memory")
#define CP_WAIT0()  asm volatile("cp.async.wait_group 0;" ::: "memory")

__device__ __forceinline__ void ldsm4(uint32_t& d0, uint32_t& d1, uint32_t& d2,
                                      uint32_t& d3, uint32_t addr) {
    asm volatile("ldmatrix.sync.aligned.m8n8.x4.shared.b16 {%0,%1,%2,%3}, [%4];"
                 : "=r"(d0), "=r"(d1), "=r"(d2), "=r"(d3) : "r"(addr));
}

// Fill a 128x64-half tile into smem stage. 16B cp.async x8, 128 thr.
__device__ __forceinline__ void fill_async(uint32_t smdst, const __half* __restrict__ src,
                                           int rstride, int tid) {
#pragma unroll
    for (int q = 0; q < 8; q++) {
        int idx = q * 128 + tid;
        int r = idx >> 3;             // row 0..127
        int s = (idx & 7) << 3;       // half offset 0..56
        cpa16(smdst + (uint32_t)(r * PADH + s) * 2, src + (size_t)r * rstride + s);
    }
}

// Per-lane ldmatrix byte offsets within a tile.
__device__ __forceinline__ uint32_t lane_a(int lane) {
    return (uint32_t)(((lane & 15) * PADH + (lane >> 4) * 8) * 2);
}
__device__ __forceinline__ uint32_t lane_b(int lane) {
    int row = (lane & 7) + ((lane & 16) ? 8 : 0);
    int kh = ((lane >> 3) & 1) * 8;
    return (uint32_t)((row * PADH + kh) * 2);
}

// One K=64 chunk of 128x128 MMA (fp16 m16n8k16 x4) via ldmatrix.
__device__ __forceinline__ void mma_chunk(uint32_t aaddr, uint32_t baddr,
                                          float acc[4][8][4]) {
#pragma unroll
    for (int kk = 0; kk < 4; kk++) {
        uint32_t a[4][4];
#pragma unroll
        for (int mt = 0; mt < 4; mt++)
            ldsm4(a[mt][0], a[mt][1], a[mt][2], a[mt][3],
                  aaddr + (uint32_t)((mt * 16 * PADH + kk * 16) * 2));
        uint32_t bf[4][4];
#pragma unroll
        for (int np = 0; np < 4; np++)
            ldsm4(bf[np][0], bf[np][1], bf[np][2], bf[np][3],
                  baddr + (uint32_t)((np * 16 * PADH + kk * 16) * 2));
#pragma unroll
        for (int nt = 0; nt < 8; nt++) {
            uint32_t b0 = bf[nt >> 1][(nt & 1) * 2];
            uint32_t b1 = bf[nt >> 1][(nt & 1) * 2 + 1];
#pragma unroll
            for (int mt = 0; mt < 4; mt++) {
                asm volatile(
                    "mma.sync.aligned.m16n8k16.row.col.f32.f16.f16.f32 "
                    "{%0,%1,%2,%3}, {%4,%5,%6,%7}, {%8,%9}, {%0,%1,%2,%3};"
                    : "+f"(acc[mt][nt][0]), "+f"(acc[mt][nt][1]),
                      "+f"(acc[mt][nt][2]), "+f"(acc[mt][nt][3])
                    : "r"(a[mt][0]), "r"(a[mt][1]), "r"(a[mt][2]), "r"(a[mt][3]),
                      "r"(b0), "r"(b1));
            }
        }
    }
}

__device__ __forceinline__ void acc_scale(float acc[4][8][4], float s) {
#pragma unroll
    for (int m = 0; m < 4; m++)
#pragma unroll
        for (int n = 0; n < 8; n++)
#pragma unroll
            for (int e = 0; e < 4; e++) acc[m][n][e] *= s;
}

#define ACC_INIT(acc) \
    _Pragma("unroll") for (int _m = 0; _m < 4; _m++) \
    _Pragma("unroll") for (int _n = 0; _n < 8; _n++) \
    _Pragma("unroll") for (int _e = 0; _e < 4; _e++) acc[_m][_n][_e] = 0.f;

// ---------------- h = [zeros ; x@input_w + input_b] (fp16) ----------------
__global__ void k_input(const float* __restrict__ x, const float* __restrict__ iw,
                        const float* __restrict__ ib) {
    int idx = blockIdx.x * blockDim.x + threadIdx.x;
    if (idx >= Bb * TPAD * Vv * Cc) return;
    int c = idx & 127;
    int rest = idx >> 7;
    int v = rest & 511;
    int bt = rest >> 9;
    int tp = bt % TPAD;
    int b  = bt / TPAD;
    float val = 0.f;
    if (tp >= BETA) {
        float xv = x[(b * Tt + (tp - BETA)) * Vv + v];
        val = xv * iw[c] + ib[c];
    }
    g_ht[idx] = __float2half_rn(val);
}

// ---------------- h [v][c] -> hT [c][v], 32x32 half tiles ----------------
__global__ void k_transp(int active) {
    __shared__ __half tile[32][34];
    int z = blockIdx.z;
    int slab = active ? ((z / Tt) * TPAD + BETA + (z % Tt)) : z;
    int c0 = blockIdx.x * 32, v0 = blockIdx.y * 32;
    int tx = threadIdx.x, ty = threadIdx.y;
    const __half* src = g_ht + (size_t)slab * Vv * Cc;
#pragma unroll
    for (int r = 0; r < 4; r++)
        tile[ty + 8 * r][tx] = src[(size_t)(v0 + ty + 8 * r) * Cc + c0 + tx];
    __syncthreads();
    __half* dst = g_hTt + (size_t)slab * Cc * Vv;
#pragma unroll
    for (int r = 0; r < 4; r++)
        dst[(size_t)(c0 + ty + 8 * r) * Vv + v0 + tx] = tile[tx][ty + 8 * r];
}

// ---------------- weight conversions (once) ----------------
__global__ void k_cvtW(const float* __restrict__ xw, const float* __restrict__ fs0,
                       const float* __restrict__ fsl, const float* __restrict__ gw,
                       const float* __restrict__ glu0, const float* __restrict__ glul) {
    int idx = blockIdx.x * blockDim.x + threadIdx.x;
    const int N1 = LL * C2 * Cc;
    const int N2 = 4 * Cc * KTC;
    const int N3 = 1024 * 512;
    const int N4 = 4 * Cc * C2;
    if (idx < N1) {
        int l = idx / (C2 * Cc);
        int n = (idx / Cc) % C2;
        int k = idx % Cc;
        g_xwTt[idx] = __float2half_rn(xw[((size_t)l * Cc + k) * C2 + n]);
    } else if (idx < N1 + N2) {
        int j = idx - N1;
        int s = j / (Cc * KTC);
        int r = j % (Cc * KTC);
        float v = (s == 0) ? fs0[r] : fsl[(size_t)(s - 1) * Cc * KTC + r];
        g_fwt[j] = __float2half_rn(v);
    } else if (idx < N1 + N2 + N3) {
        int j = idx - N1 - N2;
        g_gwt[j] = __float2half_rn(gw[j]);
    } else if (idx < N1 + N2 + N3 + N4) {
        int j = idx - N1 - N2 - N3;          // [s][c][o]
        int s = j / (Cc * C2);
        int c = (j / C2) % Cc;
        int o = j % C2;
        float v = (s == 0) ? glu0[(size_t)o * Cc + c]
                           : glul[((size_t)(s - 1) * C2 + o) * Cc + c];
        g_gluwT[j] = v;
    }
}

// ---------------- E (fp16) ----------------
__global__ void k_buildE(const float* __restrict__ sape, const float* __restrict__ srpe,
                         const float* __restrict__ trpe, const float* __restrict__ mask,
                         const float* __restrict__ mus, const float* __restrict__ isgs) {
    int blk = blockIdx.x;
    int l = blk / (Vv * 3);
    int rem = blk % (Vv * 3);
    int j = rem / 3, k = rem % 3;
    int i = threadIdx.x;
    __shared__ float mu[48], is[48];
    if (threadIdx.x < 48) { mu[threadIdx.x] = mus[l * 48 + threadIdx.x];
                            is[threadIdx.x] = isgs[l * 48 + threadIdx.x]; }
    __syncthreads();
    float gi = 0.f, gj = 0.f, ge = 0.f, gtr = 0.f;
#pragma unroll
    for (int q = 0; q < 8; q++) {
        float df;
        df = sape[i * 8 + q] - mu[q];        gi  += -0.5f * df * df * is[q] * is[q];
        df = sape[j * 8 + q] - mu[8 + q];    gj  += -0.5f * df * df * is[8 + q] * is[8 + q];
        df = srpe[((size_t)i * Vv + j) * 8 + q] - mu[32 + q];
                                             ge  += -0.5f * df * df * is[32 + q] * is[32 + q];
        df = trpe[k * 8 + q] - mu[40 + q];   gtr += -0.5f * df * df * is[40 + q] * is[40 + q];
    }
    float m = mask[j * KV + k * Vv + i];
    g_Et[((size_t)l * Vv + j) * KV + k * Vv + i] =
        __float2half_rn(m * expf(gi + gj + ge + gtr));
}

// ---------------- SEP / TEP ----------------
__global__ void k_septep(const float* __restrict__ sape, const float* __restrict__ tape,
                         const float* __restrict__ sew, const float* __restrict__ tew,
                         const float* __restrict__ xpb) {
    int idx = blockIdx.x * blockDim.x + threadIdx.x;
    const int NSEP = LL * Vv * C2;
    const int NTEP = LL * BT * C2;
    if (idx < NSEP) {
        int l = idx / (Vv * C2);
        int v = (idx / C2) % Vv;
        int c2 = idx % C2;
        float acc = 0.f;
#pragma unroll
        for (int q = 0; q < 8; q++) acc += sape[v * 8 + q] * sew[(l * 8 + q) * C2 + c2];
        g_sep[idx] = acc;
    } else if (idx < NSEP + NTEP) {
        int jdx = idx - NSEP;
        int l = jdx / (BT * C2);
        int bt = (jdx / C2) % BT;
        int c2 = jdx % C2;
        float acc = xpb[l * C2 + c2];
#pragma unroll
        for (int q = 0; q < 8; q++) acc += tape[bt * 8 + q] * tew[(l * 8 + q) * C2 + c2];
        g_tep[jdx] = acc;
    }
}

// ============ pipelined MMA GEMMs (single-sync 2-stage, K64) ============

// agg partial: split ks covers K64 chunks [ks*12, ks*12+12). Output fp32, ascal applied.
__global__ __launch_bounds__(128, 3) void k_agg_mma(int l, const float* __restrict__ tape,
                                                    const float* __restrict__ mus,
                                                    const float* __restrict__ isgs) {
    extern __shared__ __align__(16) uint32_t smp[];
    uint32_t smb = smem_u32(smp);
    int tid = threadIdx.x;
    int wid = tid >> 5, lane = tid & 31;
    int wm = wid >> 1, wn = wid & 1;
    int bt = blockIdx.y, b = bt / Tt, t = bt % Tt;
    int j0 = blockIdx.x * 128;
    int ks = blockIdx.z;
    float acc[4][8][4];
    ACC_INIT(acc);
    uint32_t awoff = (uint32_t)(wm * 64 * PADH * 2) + lane_a(lane);
    uint32_t bwoff = TILE_BYTES + (uint32_t)(wn * 64 * PADH * 2) + lane_b(lane);

    float wks[3], ascal;
    {
        const float* mu2 = mus + (l * 6 + 2) * 8; const float* is2 = isgs + (l * 6 + 2) * 8;
        const float* mu3 = mus + (l * 6 + 3) * 8; const float* is3 = isgs + (l * 6 + 3) * 8;
        const float* tp = tape + bt * 8;
        float gti = 0.f;
#pragma unroll
        for (int q = 0; q < 8; q++) { float df = tp[q] - mu2[q]; gti += -0.5f * df * df * is2[q] * is2[q]; }
        ascal = expf(gti);
#pragma unroll
        for (int k = 0; k < 3; k++) {
            int s = t + k;
            float gtj = 0.f;
#pragma unroll
            for (int q = 0; q < 8; q++) {
                float e = (s < BETA) ? 0.f : tape[(b * Tt + (s - BETA)) * 8 + q];
                float df = e - mu3[q];
                gtj += -0.5f * df * df * is3[q] * is3[q];
            }
            wks[k] = expf(gtj);
        }
    }

    const __half* Abase = g_Et + ((size_t)l * Vv + j0) * KV;
    const __half* Hbase = g_hTt + (size_t)(b * TPAD + t) * Cc * Vv;

    const int NCH = 12;
    int base = ks * NCH;
    {
        int gc = base;
        int k = gc >> 3, i0 = (gc & 7) * 64;
        fill_async(smb, Abase + gc * 64, KV, tid);
        fill_async(smb + TILE_BYTES, Hbase + (size_t)k * Cc * Vv + i0, Vv, tid);
        CP_COMMIT();
    }
    for (int ch = 0; ch < NCH; ch++) {
        int gc = base + ch;
        CP_WAIT0();
        __syncthreads();
        if (ch + 1 < NCH) {
            int ngc = gc + 1;
            int k = ngc >> 3, i0 = (ngc & 7) * 64;
            uint32_t so = (uint32_t)((ch + 1) & 1) * 2 * TILE_BYTES;
            fill_async(smb + so, Abase + ngc * 64, KV, tid);
            fill_async(smb + so + TILE_BYTES, Hbase + (size_t)k * Cc * Vv + i0, Vv, tid);
            CP_COMMIT();
        }
        uint32_t st = smb + (uint32_t)(ch & 1) * 2 * TILE_BYTES;
        mma_chunk(st + awoff, st + bwoff, acc);
        if (gc == 7)  acc_scale(acc, wks[0] / wks[1]);
        if (gc == 15) acc_scale(acc, wks[1] / wks[2]);
    }
    float fs = ((ks == 0) ? wks[1] : wks[2]) * ascal;
    int g = lane >> 2, c = lane & 3;
    float* part = g_aggp + (size_t)ks * BT * Vv * Cc;
#pragma unroll
    for (int mt = 0; mt < 4; mt++) {
#pragma unroll
        for (int nt = 0; nt < 8; nt++) {
            int row = wm * 64 + mt * 16 + g;
            int col = wn * 64 + nt * 8 + 2 * c;
            float* d0 = part + ((size_t)bt * Vv + j0 + row) * Cc + col;
            float* d1 = d0 + 8 * Cc;
            *(float2*)d0 = make_float2(acc[mt][nt][0] * fs, acc[mt][nt][1] * fs);
            *(float2*)d1 = make_float2(acc[mt][nt][2] * fs, acc[mt][nt][3] * fs);
        }
    }
}

// z = (aggp0+aggp1) @ xproj_w[l]: M=BT*V, N=256, K=128 (2 K64 chunks).
__device__ __forceinline__ void fill_aggA(uint32_t* As, int m0, int ch, int tid) {
    const float* p0 = g_aggp + (size_t)m0 * Cc + ch * 64;
    const float* p1 = p0 + (size_t)BT * Vv * Cc;
#pragma unroll
    for (int q = 0; q < 8; q++) {
        int idx = q * 128 + tid;
        int r = idx >> 3;
        int s = (idx & 7) << 3;
        const float* a0 = p0 + (size_t)r * Cc + s;
        const float* b0 = p1 + (size_t)r * Cc + s;
        float4 a = *(const float4*)a0, a2 = *(const float4*)(a0 + 4);
        float4 b = *(const float4*)b0, b2 = *(const float4*)(b0 + 4);
        uint4 u;
        u.x = pack2(a.x + b.x, a.y + b.y);
        u.y = pack2(a.z + b.z, a.w + b.w);
        u.z = pack2(a2.x + b2.x, a2.y + b2.y);
        u.w = pack2(a2.z + b2.z, a2.w + b2.w);
        *(uint4*)(As + r * PADW + (s >> 1)) = u;
    }
}

__global__ __launch_bounds__(128, 3) void k_zgemm_mma(int l) {
    extern __shared__ __align__(16) uint32_t smp[];
    uint32_t smb = smem_u32(smp);
    int tid = threadIdx.x;
    int wid = tid >> 5, lane = tid & 31;
    int wm = wid >> 1, wn = wid & 1;
    int m0 = blockIdx.x * 128;
    int n0 = blockIdx.y * 128;
    float acc[4][8][4];
    ACC_INIT(acc);
    uint32_t awoff = (uint32_t)(wm * 64 * PADH * 2) + lane_a(lane);
    uint32_t bwoff = TILE_BYTES + (uint32_t)(wn * 64 * PADH * 2) + lane_b(lane);
    const __half* Bbase = g_xwTt + (size_t)l * C2 * Cc + (size_t)n0 * Cc;

    fill_async(smb + TILE_BYTES, Bbase, Cc, tid);
    CP_COMMIT();
    fill_aggA(smp, m0, 0, tid);
    const int NCH = 2;
    for (int ch = 0; ch < NCH; ch++) {
        CP_WAIT0();
        __syncthreads();
        if (ch + 1 < NCH) {
            uint32_t so = (uint32_t)((ch + 1) & 1) * 2 * TILE_BYTES;
            fill_async(smb + so + TILE_BYTES, Bbase + (ch + 1) * 64, Cc, tid);
            CP_COMMIT();
            fill_aggA(smp + (size_t)((ch + 1) & 1) * 2 * TILE_WORDS, m0, ch + 1, tid);
        }
        uint32_t st = smb + (uint32_t)(ch & 1) * 2 * TILE_BYTES;
        mma_chunk(st + awoff, st + bwoff, acc);
        if (ch + 1 < NCH) __syncthreads();   // fill_aggA STS visibility for others' mma(ch+1)
    }
    int g = lane >> 2, c = lane & 3;
#pragma unroll
    for (int mt = 0; mt < 4; mt++) {
#pragma unroll
        for (int nt = 0; nt < 8; nt++) {
            int row = wm * 64 + mt * 16 + g;
            int col = wn * 64 + nt * 8 + 2 * c;
            float* d0 = g_z + (size_t)(m0 + row) * C2 + n0 + col;
            float* d1 = d0 + 8 * C2;
            *(float2*)d0 = make_float2(acc[mt][nt][0], acc[mt][nt][1]);
            *(float2*)d1 = make_float2(acc[mt][nt][2], acc[mt][nt][3]);
        }
    }
}

// GFS fc split-K: partial[ks][b][v][o] (fp16) over K64 chunks [ks*4, ks*4+4)
__global__ __launch_bounds__(128, 3) void k_gfs_mma(int sidx) {
    extern __shared__ __align__(16) uint32_t smp[];
    uint32_t smb = smem_u32(smp);
    int tid = threadIdx.x;
    int wid = tid >> 5, lane = tid & 31;
    int wm = wid >> 1, wn = wid & 1;
    int v0 = blockIdx.x * 128;
    int b = blockIdx.y;
    int ks = blockIdx.z;
    float acc[4][8][4];
    ACC_INIT(acc);
    uint32_t awoff = (uint32_t)(wm * 64 * PADH * 2) + lane_a(lane);
    uint32_t bwoff = TILE_BYTES + (uint32_t)(wn * 64 * PADH * 2) + lane_b(lane);
    const __half* fw = g_fwt + (size_t)sidx * Cc * KTC;

    auto asrc = [&](int gch) -> const __half* {
        int t = gch >> 1, coff = (gch & 1) * 64;
        return g_ht + ((size_t)(b * TPAD + BETA + t) * Vv + v0) * Cc + coff;
    };
    int g0 = ks * 4;
    fill_async(smb, asrc(g0), Cc, tid);
    fill_async(smb + TILE_BYTES, fw + g0 * 64, KTC, tid);
    CP_COMMIT();
    const int NCH = 4;
    for (int ch = 0; ch < NCH; ch++) {
        CP_WAIT0();
        __syncthreads();
        if (ch + 1 < NCH) {
            int nc = g0 + ch + 1;
            uint32_t so = (uint32_t)((ch + 1) & 1) * 2 * TILE_BYTES;
            fill_async(smb + so, asrc(nc), Cc, tid);
            fill_async(smb + so + TILE_BYTES, fw + nc * 64, KTC, tid);
            CP_COMMIT();
        }
        uint32_t st = smb + (uint32_t)(ch & 1) * 2 * TILE_BYTES;
        mma_chunk(st + awoff, st + bwoff, acc);
    }
    int g = lane >> 2, c = lane & 3;
    __half* part = g_spart + ((size_t)ks * Bb + b) * Vv * Cc;
#pragma unroll
    for (int mt = 0; mt < 4; mt++) {
#pragma unroll
        for (int nt = 0; nt < 8; nt++) {
            int row = wm * 64 + mt * 16 + g;
            int col = wn * 64 + nt * 8 + 2 * c;
            uint32_t* d0 = (uint32_t*)(part + (size_t)(v0 + row) * Cc + col);
            uint32_t* d1 = (uint32_t*)(part + (size_t)(v0 + row + 8) * Cc + col);
            *d0 = pack2(acc[mt][nt][0], acc[mt][nt][1]);
            *d1 = pack2(acc[mt][nt][2], acc[mt][nt][3]);
        }
    }
}

// head: g[b][p][v] = gb[p] + sum_o gw[p][o]*skipT[b][v][o] (8 K64 chunks)
__global__ __launch_bounds__(128, 3) void k_headg_mma(const float* __restrict__ gb) {
    extern __shared__ __align__(16) uint32_t smp[];
    uint32_t smb = smem_u32(smp);
    int tid = threadIdx.x;
    int wid = tid >> 5, lane = tid & 31;
    int wm = wid >> 1, wn = wid & 1;
    int p0 = blockIdx.x * 128;
    int b = blockIdx.y >> 2;
    int n0 = (blockIdx.y & 3) * 128;
    float acc[4][8][4];
    ACC_INIT(acc);
    uint32_t awoff = (uint32_t)(wm * 64 * PADH * 2) + lane_a(lane);
    uint32_t bwoff = TILE_BYTES + (uint32_t)(wn * 64 * PADH * 2) + lane_b(lane);
    const __half* Abase = g_gwt + (size_t)p0 * 512;
    const __half* Bbase = g_skipTt + ((size_t)b * Vv + n0) * 512;

    fill_async(smb, Abase, 512, tid);
    fill_async(smb + TILE_BYTES, Bbase, 512, tid);
    CP_COMMIT();
    const int NCH = 8;
    for (int ch = 0; ch < NCH; ch++) {
        CP_WAIT0();
        __syncthreads();
        if (ch + 1 < NCH) {
            uint32_t so = (uint32_t)((ch + 1) & 1) * 2 * TILE_BYTES;
            fill_async(smb + so, Abase + (ch + 1) * 64, 512, tid);
            fill_async(smb + so + TILE_BYTES, Bbase + (ch + 1) * 64, 512, tid);
            CP_COMMIT();
        }
        uint32_t st = smb + (uint32_t)(ch & 1) * 2 * TILE_BYTES;
        mma_chunk(st + awoff, st + bwoff, acc);
    }
    int g = lane >> 2, c = lane & 3;
#pragma unroll
    for (int mt = 0; mt < 4; mt++) {
#pragma unroll
        for (int nt = 0; nt < 8; nt++) {
            int row = wm * 64 + mt * 16 + g;
            int col = wn * 64 + nt * 8 + 2 * c;
            float bi0 = gb[p0 + row], bi1 = gb[p0 + row + 8];
            float* d0 = g_g + ((size_t)b * 1024 + p0 + row) * Vv + n0 + col;
            float* d1 = d0 + 8 * Vv;
            *(float2*)d0 = make_float2(acc[mt][nt][0] + bi0, acc[mt][nt][1] + bi0);
            *(float2*)d1 = make_float2(acc[mt][nt][2] + bi1, acc[mt][nt][3] + bi1);
        }
    }
}

// ---- fused add + LayerNorm + GLU -> h (fp16) ----
__global__ __launch_bounds__(256) void k_lnglu(int l, const float* __restrict__ lng,
                                               const float* __restrict__ lnb) {
    int w = threadIdx.x >> 5, lane = threadIdx.x & 31;
    int row = blockIdx.x * 8 + w;
    int bt = row >> 9, v = row & 511;
    int b = bt / Tt, t = bt % Tt;
    const float* zr = g_z + (size_t)row * C2;
    const float* sp = g_sep + ((size_t)l * Vv + v) * C2;
    const float* tp = g_tep + ((size_t)l * BT + bt) * C2;
    float val[8];
    float sum = 0.f;
#pragma unroll
    for (int q = 0; q < 8; q++) {
        int c2 = q * 32 + lane;
        val[q] = zr[c2] + sp[c2] + tp[c2];
        sum += val[q];
    }
#pragma unroll
    for (int o = 16; o; o >>= 1) sum += __shfl_xor_sync(0xffffffffu, sum, o);
    float mean = sum * (1.f / 256.f);
    float s2 = 0.f;
#pragma unroll
    for (int q = 0; q < 8; q++) { float df = val[q] - mean; s2 += df * df; }
#pragma unroll
    for (int o = 16; o; o >>= 1) s2 += __shfl_xor_sync(0xffffffffu, s2, o);
    float rstd = rsqrtf(s2 * (1.f / 256.f) + 1e-5f);
    float y[8];
#pragma unroll
    for (int q = 0; q < 8; q++) {
        int c2 = q * 32 + lane;
        y[q] = (val[q] - mean) * rstd * lng[l * C2 + c2] + lnb[l * C2 + c2];
    }
    size_t slab = (size_t)(b * TPAD + BETA + t);
    __half* hp = g_ht + (slab * Vv + v) * Cc;
#pragma unroll
    for (int q = 0; q < 4; q++)
        hp[q * 32 + lane] = __float2half_rn(y[q] * sigm(y[q + 4]));
}

// ---- GFS GLU (fused fp16 split-K reduce + bias; coalesced weights) ----
__global__ __launch_bounds__(128) void k_gfs_glu(int slot, const float* __restrict__ gb,
                                                 const float* __restrict__ fb) {
    int b = blockIdx.x >> 6;
    int v0 = (blockIdx.x & 63) * 8;
    __shared__ float s8[8][128];
    int o = threadIdx.x;
    float fbias = fb[o];
#pragma unroll
    for (int vi = 0; vi < 8; vi++) {
        float acc = fbias;
#pragma unroll
        for (int ks = 0; ks < KSPL; ks++)
            acc += __half2float(
                g_spart[(((size_t)ks * Bb + b) * Vv + v0 + vi) * Cc + o]);
        s8[vi][o] = acc;
    }
    __syncthreads();
    float al[8], ar[8];
    float bl = gb[o], br = gb[o + 128];
#pragma unroll
    for (int vi = 0; vi < 8; vi++) { al[vi] = bl; ar[vi] = br; }
    const float* wT = g_gluwT + (size_t)slot * Cc * C2;
    for (int c = 0; c < 128; c++) {
        float a  = wT[(size_t)c * C2 + o];
        float bw = wT[(size_t)c * C2 + 128 + o];
#pragma unroll
        for (int vi = 0; vi < 8; vi++) {
            float sv = s8[vi][c];
            al[vi] += a * sv;
            ar[vi] += bw * sv;
        }
    }
#pragma unroll
    for (int vi = 0; vi < 8; vi++)
        g_skipTt[((size_t)b * Vv + v0 + vi) * 512 + slot * 128 + o] =
            __float2half_rn(al[vi] * sigm(ar[vi]));
}

// ---- output head (split q) ----
__global__ __launch_bounds__(512) void k_out_part(const float* __restrict__ ow) {
    __shared__ float ws[PP * 128];
    int b = blockIdx.x;
    int qs = blockIdx.y;
    int v = threadIdx.x;
    for (int i = v; i < PP * 128; i += 512) {
        int r = i >> 7, qq = i & 127;
        ws[i] = ow[r * 512 + qs * 128 + qq];
    }
    __syncthreads();
    float acc[PP];
#pragma unroll
    for (int r = 0; r < PP; r++) acc[r] = 0.f;
    const float* gB = g_g + (size_t)b * 1024 * Vv;
    for (int qq = 0; qq < 128; qq++) {
        int q = qs * 128 + qq;
        float gl = gB[(size_t)q * Vv + v];
        float gr = gB[(size_t)(512 + q) * Vv + v];
        float gate = gl * sigm(gr);
#pragma unroll
        for (int r = 0; r < PP; r++) acc[r] += ws[r * 128 + qq] * gate;
    }
#pragma unroll
    for (int r = 0; r < PP; r++)
        g_opart[(((size_t)qs * Bb + b) * PP + r) * Vv + v] = acc[r];
}

__global__ void k_out_red(const float* __restrict__ ob, float* __restrict__ out) {
    int idx = blockIdx.x * blockDim.x + threadIdx.x;
    if (idx >= Bb * PP * Vv) return;
    int r = (idx / Vv) % PP;
    float s = ob[r];
#pragma unroll
    for (int qs = 0; qs < QSPL; qs++)
        s += g_opart[(size_t)qs * Bb * PP * Vv + idx];
    out[idx] = s;
}

// ---------------- orchestration ----------------
extern "C" void kernel_launch(void* const* d_in, const int* in_sizes, int n_in,
                              void* d_out, int out_size) {
    const float* x          = (const float*)d_in[0];
    const float* sape       = (const float*)d_in[1];
    const float* tape       = (const float*)d_in[2];
    const float* srpe       = (const float*)d_in[3];
    const float* trpe       = (const float*)d_in[4];
    const float* range_mask = (const float*)d_in[7];
    const float* input_w    = (const float*)d_in[8];
    const float* input_b    = (const float*)d_in[9];
    const float* fs0_fc_w   = (const float*)d_in[10];
    const float* fs0_fc_b   = (const float*)d_in[11];
    const float* fs0_glu_w  = (const float*)d_in[12];
    const float* fs0_glu_b  = (const float*)d_in[13];
    const float* mus        = (const float*)d_in[14];
    const float* isgs       = (const float*)d_in[15];
    const float* xproj_w    = (const float*)d_in[16];
    const float* xproj_b    = (const float*)d_in[17];
    const float* seproj_w   = (const float*)d_in[18];
    const float* teproj_w   = (const float*)d_in[19];
    const float* ln_g       = (const float*)d_in[20];
    const float* ln_b       = (const float*)d_in[21];
    const float* fs_fc_w    = (const float*)d_in[22];
    const float* fs_fc_b    = (const float*)d_in[23];
    const float* fs_glu_w   = (const float*)d_in[24];
    const float* fs_glu_b   = (const float*)d_in[25];
    const float* glu_w      = (const float*)d_in[26];
    const float* glu_b      = (const float*)d_in[27];
    const float* out_w      = (const float*)d_in[28];
    const float* out_b      = (const float*)d_in[29];
    float* out = (float*)d_out;

    cudaFuncSetAttribute(k_agg_mma,   cudaFuncAttributeMaxDynamicSharedMemorySize, SMEM_PIPE);
    cudaFuncSetAttribute(k_zgemm_mma, cudaFuncAttributeMaxDynamicSharedMemorySize, SMEM_PIPE);
    cudaFuncSetAttribute(k_gfs_mma,   cudaFuncAttributeMaxDynamicSharedMemorySize, SMEM_PIPE);
    cudaFuncSetAttribute(k_headg_mma, cudaFuncAttributeMaxDynamicSharedMemorySize, SMEM_PIPE);

    // slots 1..3 = prerequisites for agg(0); slot 4 = k_agg_mma(0) (profiled)
    k_input<<<(Bb * TPAD * Vv * Cc) / 256, 256>>>(x, input_w, input_b);
    k_transp<<<dim3(4, 16, Bb * TPAD), dim3(32, 8)>>>(0);
    k_buildE<<<LL * Vv * TSZ, 512>>>(sape, srpe, trpe, range_mask, mus, isgs);
    k_agg_mma<<<dim3(4, BT, ASPL), 128, SMEM_PIPE>>>(0, tape, mus, isgs);

    // remaining setup
    {
        int n = LL * C2 * Cc + 4 * Cc * KTC + 1024 * 512 + 4 * Cc * C2;
        k_cvtW<<<(n + 255) / 256, 256>>>(xproj_w, fs0_fc_w, fs_fc_w, glu_w,
                                         fs0_glu_w, fs_glu_w);
    }
    {
        int n = LL * Vv * C2 + LL * BT * C2;
        k_septep<<<(n + 255) / 256, 256>>>(sape, tape, seproj_w, teproj_w, xproj_b);
    }

    // skip slot 0 (uses pre-layer h; must precede lnglu(0))
    k_gfs_mma<<<dim3(4, Bb, KSPL), 128, SMEM_PIPE>>>(0);
    k_gfs_glu<<<Bb * 64, 128>>>(0, fs0_glu_b, fs0_fc_b);

    for (int l = 0; l < LL; l++) {
        if (l > 0) k_agg_mma<<<dim3(4, BT, ASPL), 128, SMEM_PIPE>>>(l, tape, mus, isgs);
        k_zgemm_mma<<<dim3(BT * Vv / 128, 2), 128, SMEM_PIPE>>>(l);
        k_lnglu<<<BT * Vv / 8, 256>>>(l, ln_g, ln_b);
        if (l < LL - 1)
            k_transp<<<dim3(4, 16, BT), dim3(32, 8)>>>(1);
        k_gfs_mma<<<dim3(4, Bb, KSPL), 128, SMEM_PIPE>>>(l + 1);
        k_gfs_glu<<<Bb * 64, 128>>>(l + 1, fs_glu_b + l * 2 * Cc, fs_fc_b + l * Cc);
    }

    // head
    k_headg_mma<<<dim3(8, 32), 128, SMEM_PIPE>>>(glu_b);
    k_out_part<<<dim3(Bb, QSPL), 512>>>(out_w);
    k_out_red<<<(Bb * PP * Vv + 255) / 256, 256>>>(out_b, out);
}

// round 17
// speedup vs baseline: 1.0590x; 1.0590x over previous
#include <cuda_runtime.h>
#include <cuda_fp16.h>
#include <math.h>
#include <cstdint>

// ---------------- problem constants ----------------
#define Bb   8
#define Tt   12
#define Vv   512
#define Cc   128
#define TSZ  3
#define LL   3
#define PP   12
#define BETA 2
#define TPAD (Tt + BETA)   // 14
#define C2   256
#define KV   (TSZ * Vv)    // 1536
#define KTC  (Tt * Cc)     // 1536
#define BT   (Bb * Tt)     // 96
#define KSPL 6             // gfs split-K
#define QSPL 4             // out split-q
#define ASPL 2             // agg split-K

#define PADH 72                             // halves per smem row (36 words), K=64 chunks
#define PADW (PADH / 2)                     // 36 words
#define TILE_WORDS (128 * PADW)             // 4608
#define TILE_BYTES (TILE_WORDS * 4)         // 18432
#define SMEM_PIPE  (4 * TILE_BYTES)         // 73728 (2 stages x A,B)

// ---------------- device scratch (static; no runtime alloc) ----------------
__device__ __align__(16) __half g_ht [Bb * TPAD * Vv * Cc];   // fp16 h [b][tp][v][c]
__device__ __align__(16) __half g_hTt[Bb * TPAD * Cc * Vv];   // fp16 h [b][tp][c][v]
__device__ __align__(16) __half g_Et [LL * Vv * KV];          // fp16 E
__device__ __align__(16) __half g_aggp[ASPL * BT * Vv * Cc];  // fp16 agg partials
__device__ __align__(16) __half g_z[BT * Vv * C2];            // fp16 z
__device__ __align__(16) __half g_spart[KSPL * Bb * Vv * Cc]; // fp16 gfs partials
__device__ __align__(16) __half g_skipTt[Bb * Vv * 512];      // fp16 [b][v][o]
__device__ __align__(16) __half g_g[Bb * 1024 * Vv];          // fp16 head pre-GLU
__device__ __align__(16) float  g_sep[LL * Vv * C2];
__device__ __align__(16) float  g_tep[LL * BT * C2];
__device__ __align__(16) __half g_xwTt[LL * C2 * Cc];         // fp16 [l][n][k]
__device__ __align__(16) __half g_fwt[4 * Cc * KTC];          // fp16 [s][o][tc]
__device__ __align__(16) __half g_gwt[1024 * 512];            // fp16 glu_w
__device__ __align__(16) float  g_gluwT[4 * Cc * C2];         // fp32 GFS GLU w, [s][c][o]
__device__ __align__(16) float  g_opart[QSPL * Bb * PP * Vv];

__device__ __forceinline__ float sigm(float x) { return 1.f / (1.f + expf(-x)); }
__device__ __forceinline__ uint32_t pack2(float lo, float hi) {
    __half2 h = __floats2half2_rn(lo, hi);
    return *reinterpret_cast<uint32_t*>(&h);
}
__device__ __forceinline__ uint32_t smem_u32(const void* p) {
    uint32_t a;
    asm("{ .reg .u64 t; cvta.to.shared.u64 t, %1; cvt.u32.u64 %0, t; }" : "=r"(a) : "l"(p));
    return a;
}
__device__ __forceinline__ void cpa16(uint32_t dst, const void* src) {
    asm volatile("cp.async.cg.shared.global [%0], [%1], 16;" :: "r"(dst), "l"(src));
}
#define CP_COMMIT() asm volatile("cp.async.commit_group;" ::: "memory")
#define CP_WAIT0()  asm volatile("cp.async.wait_group 0;" ::: "memory")
#define CP_WAIT1()  asm volatile("cp.async.wait_group 1;" ::: "memory")

__device__ __forceinline__ void ldsm4(uint32_t& d0, uint32_t& d1, uint32_t& d2,
                                      uint32_t& d3, uint32_t addr) {
    asm volatile("ldmatrix.sync.aligned.m8n8.x4.shared.b16 {%0,%1,%2,%3}, [%4];"
                 : "=r"(d0), "=r"(d1), "=r"(d2), "=r"(d3) : "r"(addr));
}

// Fill a 128x64-half tile into smem stage. 16B cp.async x8, 128 thr.
__device__ __forceinline__ void fill_async(uint32_t smdst, const __half* __restrict__ src,
                                           int rstride, int tid) {
#pragma unroll
    for (int q = 0; q < 8; q++) {
        int idx = q * 128 + tid;
        int r = idx >> 3;             // row 0..127
        int s = (idx & 7) << 3;       // half offset 0..56
        cpa16(smdst + (uint32_t)(r * PADH + s) * 2, src + (size_t)r * rstride + s);
    }
}

// Per-lane ldmatrix byte offsets within a tile.
__device__ __forceinline__ uint32_t lane_a(int lane) {
    return (uint32_t)(((lane & 15) * PADH + (lane >> 4) * 8) * 2);
}
__device__ __forceinline__ uint32_t lane_b(int lane) {
    int row = (lane & 7) + ((lane & 16) ? 8 : 0);
    int kh = ((lane >> 3) & 1) * 8;
    return (uint32_t)((row * PADH + kh) * 2);
}

// One K=64 chunk of 128x128 MMA (fp16 m16n8k16 x4) via ldmatrix.
__device__ __forceinline__ void mma_chunk(uint32_t aaddr, uint32_t baddr,
                                          float acc[4][8][4]) {
#pragma unroll
    for (int kk = 0; kk < 4; kk++) {
        uint32_t a[4][4];
#pragma unroll
        for (int mt = 0; mt < 4; mt++)
            ldsm4(a[mt][0], a[mt][1], a[mt][2], a[mt][3],
                  aaddr + (uint32_t)((mt * 16 * PADH + kk * 16) * 2));
        uint32_t bf[4][4];
#pragma unroll
        for (int np = 0; np < 4; np++)
            ldsm4(bf[np][0], bf[np][1], bf[np][2], bf[np][3],
                  baddr + (uint32_t)((np * 16 * PADH + kk * 16) * 2));
#pragma unroll
        for (int nt = 0; nt < 8; nt++) {
            uint32_t b0 = bf[nt >> 1][(nt & 1) * 2];
            uint32_t b1 = bf[nt >> 1][(nt & 1) * 2 + 1];
#pragma unroll
            for (int mt = 0; mt < 4; mt++) {
                asm volatile(
                    "mma.sync.aligned.m16n8k16.row.col.f32.f16.f16.f32 "
                    "{%0,%1,%2,%3}, {%4,%5,%6,%7}, {%8,%9}, {%0,%1,%2,%3};"
                    : "+f"(acc[mt][nt][0]), "+f"(acc[mt][nt][1]),
                      "+f"(acc[mt][nt][2]), "+f"(acc[mt][nt][3])
                    : "r"(a[mt][0]), "r"(a[mt][1]), "r"(a[mt][2]), "r"(a[mt][3]),
                      "r"(b0), "r"(b1));
            }
        }
    }
}

__device__ __forceinline__ void acc_scale(float acc[4][8][4], float s) {
#pragma unroll
    for (int m = 0; m < 4; m++)
#pragma unroll
        for (int n = 0; n < 8; n++)
#pragma unroll
            for (int e = 0; e < 4; e++) acc[m][n][e] *= s;
}

#define ACC_INIT(acc) \
    _Pragma("unroll") for (int _m = 0; _m < 4; _m++) \
    _Pragma("unroll") for (int _n = 0; _n < 8; _n++) \
    _Pragma("unroll") for (int _e = 0; _e < 4; _e++) acc[_m][_n][_e] = 0.f;

// ---------------- h = [zeros ; x@input_w + input_b] (fp16) ----------------
__global__ void k_input(const float* __restrict__ x, const float* __restrict__ iw,
                        const float* __restrict__ ib) {
    int idx = blockIdx.x * blockDim.x + threadIdx.x;
    if (idx >= Bb * TPAD * Vv * Cc) return;
    int c = idx & 127;
    int rest = idx >> 7;
    int v = rest & 511;
    int bt = rest >> 9;
    int tp = bt % TPAD;
    int b  = bt / TPAD;
    float val = 0.f;
    if (tp >= BETA) {
        float xv = x[(b * Tt + (tp - BETA)) * Vv + v];
        val = xv * iw[c] + ib[c];
    }
    g_ht[idx] = __float2half_rn(val);
}

// ---------------- h [v][c] -> hT [c][v], 32x32 half tiles ----------------
__global__ void k_transp(int active) {
    __shared__ __half tile[32][34];
    int z = blockIdx.z;
    int slab = active ? ((z / Tt) * TPAD + BETA + (z % Tt)) : z;
    int c0 = blockIdx.x * 32, v0 = blockIdx.y * 32;
    int tx = threadIdx.x, ty = threadIdx.y;
    const __half* src = g_ht + (size_t)slab * Vv * Cc;
#pragma unroll
    for (int r = 0; r < 4; r++)
        tile[ty + 8 * r][tx] = src[(size_t)(v0 + ty + 8 * r) * Cc + c0 + tx];
    __syncthreads();
    __half* dst = g_hTt + (size_t)slab * Cc * Vv;
#pragma unroll
    for (int r = 0; r < 4; r++)
        dst[(size_t)(c0 + ty + 8 * r) * Vv + v0 + tx] = tile[tx][ty + 8 * r];
}

// ---------------- weight conversions (once) ----------------
__global__ void k_cvtW(const float* __restrict__ xw, const float* __restrict__ fs0,
                       const float* __restrict__ fsl, const float* __restrict__ gw,
                       const float* __restrict__ glu0, const float* __restrict__ glul) {
    int idx = blockIdx.x * blockDim.x + threadIdx.x;
    const int N1 = LL * C2 * Cc;
    const int N2 = 4 * Cc * KTC;
    const int N3 = 1024 * 512;
    const int N4 = 4 * Cc * C2;
    if (idx < N1) {
        int l = idx / (C2 * Cc);
        int n = (idx / Cc) % C2;
        int k = idx % Cc;
        g_xwTt[idx] = __float2half_rn(xw[((size_t)l * Cc + k) * C2 + n]);
    } else if (idx < N1 + N2) {
        int j = idx - N1;
        int s = j / (Cc * KTC);
        int r = j % (Cc * KTC);
        float v = (s == 0) ? fs0[r] : fsl[(size_t)(s - 1) * Cc * KTC + r];
        g_fwt[j] = __float2half_rn(v);
    } else if (idx < N1 + N2 + N3) {
        int j = idx - N1 - N2;
        g_gwt[j] = __float2half_rn(gw[j]);
    } else if (idx < N1 + N2 + N3 + N4) {
        int j = idx - N1 - N2 - N3;          // [s][c][o]
        int s = j / (Cc * C2);
        int c = (j / C2) % Cc;
        int o = j % C2;
        float v = (s == 0) ? glu0[(size_t)o * Cc + c]
                           : glul[((size_t)(s - 1) * C2 + o) * Cc + c];
        g_gluwT[j] = v;
    }
}

// ---------------- E (fp16) ----------------
__global__ void k_buildE(const float* __restrict__ sape, const float* __restrict__ srpe,
                         const float* __restrict__ trpe, const float* __restrict__ mask,
                         const float* __restrict__ mus, const float* __restrict__ isgs) {
    int blk = blockIdx.x;
    int l = blk / (Vv * 3);
    int rem = blk % (Vv * 3);
    int j = rem / 3, k = rem % 3;
    int i = threadIdx.x;
    __shared__ float mu[48], is[48];
    if (threadIdx.x < 48) { mu[threadIdx.x] = mus[l * 48 + threadIdx.x];
                            is[threadIdx.x] = isgs[l * 48 + threadIdx.x]; }
    __syncthreads();
    float gi = 0.f, gj = 0.f, ge = 0.f, gtr = 0.f;
#pragma unroll
    for (int q = 0; q < 8; q++) {
        float df;
        df = sape[i * 8 + q] - mu[q];        gi  += -0.5f * df * df * is[q] * is[q];
        df = sape[j * 8 + q] - mu[8 + q];    gj  += -0.5f * df * df * is[8 + q] * is[8 + q];
        df = srpe[((size_t)i * Vv + j) * 8 + q] - mu[32 + q];
                                             ge  += -0.5f * df * df * is[32 + q] * is[32 + q];
        df = trpe[k * 8 + q] - mu[40 + q];   gtr += -0.5f * df * df * is[40 + q] * is[40 + q];
    }
    float m = mask[j * KV + k * Vv + i];
    g_Et[((size_t)l * Vv + j) * KV + k * Vv + i] =
        __float2half_rn(m * expf(gi + gj + ge + gtr));
}

// ---------------- SEP / TEP ----------------
__global__ void k_septep(const float* __restrict__ sape, const float* __restrict__ tape,
                         const float* __restrict__ sew, const float* __restrict__ tew,
                         const float* __restrict__ xpb) {
    int idx = blockIdx.x * blockDim.x + threadIdx.x;
    const int NSEP = LL * Vv * C2;
    const int NTEP = LL * BT * C2;
    if (idx < NSEP) {
        int l = idx / (Vv * C2);
        int v = (idx / C2) % Vv;
        int c2 = idx % C2;
        float acc = 0.f;
#pragma unroll
        for (int q = 0; q < 8; q++) acc += sape[v * 8 + q] * sew[(l * 8 + q) * C2 + c2];
        g_sep[idx] = acc;
    } else if (idx < NSEP + NTEP) {
        int jdx = idx - NSEP;
        int l = jdx / (BT * C2);
        int bt = (jdx / C2) % BT;
        int c2 = jdx % C2;
        float acc = xpb[l * C2 + c2];
#pragma unroll
        for (int q = 0; q < 8; q++) acc += tape[bt * 8 + q] * tew[(l * 8 + q) * C2 + c2];
        g_tep[jdx] = acc;
    }
}

// ============ pipelined MMA GEMMs (two-sync 2-stage, K64) ============

// agg partial: split ks covers K64 chunks [ks*12, ks*12+12). Output fp16, ascal applied.
__global__ __launch_bounds__(128, 3) void k_agg_mma(int l, const float* __restrict__ tape,
                                                    const float* __restrict__ mus,
                                                    const float* __restrict__ isgs) {
    extern __shared__ __align__(16) uint32_t smp[];
    uint32_t smb = smem_u32(smp);
    int tid = threadIdx.x;
    int wid = tid >> 5, lane = tid & 31;
    int wm = wid >> 1, wn = wid & 1;
    int bt = blockIdx.y, b = bt / Tt, t = bt % Tt;
    int j0 = blockIdx.x * 128;
    int ks = blockIdx.z;
    float acc[4][8][4];
    ACC_INIT(acc);
    uint32_t awoff = (uint32_t)(wm * 64 * PADH * 2) + lane_a(lane);
    uint32_t bwoff = TILE_BYTES + (uint32_t)(wn * 64 * PADH * 2) + lane_b(lane);

    float wks[3], ascal;
    {
        const float* mu2 = mus + (l * 6 + 2) * 8; const float* is2 = isgs + (l * 6 + 2) * 8;
        const float* mu3 = mus + (l * 6 + 3) * 8; const float* is3 = isgs + (l * 6 + 3) * 8;
        const float* tp = tape + bt * 8;
        float gti = 0.f;
#pragma unroll
        for (int q = 0; q < 8; q++) { float df = tp[q] - mu2[q]; gti += -0.5f * df * df * is2[q] * is2[q]; }
        ascal = expf(gti);
#pragma unroll
        for (int k = 0; k < 3; k++) {
            int s = t + k;
            float gtj = 0.f;
#pragma unroll
            for (int q = 0; q < 8; q++) {
                float e = (s < BETA) ? 0.f : tape[(b * Tt + (s - BETA)) * 8 + q];
                float df = e - mu3[q];
                gtj += -0.5f * df * df * is3[q] * is3[q];
            }
            wks[k] = expf(gtj);
        }
    }

    const __half* Abase = g_Et + ((size_t)l * Vv + j0) * KV;
    const __half* Hbase = g_hTt + (size_t)(b * TPAD + t) * Cc * Vv;

    const int NCH = 12;
    int base = ks * NCH;
    {
        int gc = base;
        int k = gc >> 3, i0 = (gc & 7) * 64;
        fill_async(smb, Abase + gc * 64, KV, tid);
        fill_async(smb + TILE_BYTES, Hbase + (size_t)k * Cc * Vv + i0, Vv, tid);
        CP_COMMIT();
    }
    for (int ch = 0; ch < NCH; ch++) {
        int gc = base + ch;
        if (ch + 1 < NCH) {
            int ngc = gc + 1;
            int k = ngc >> 3, i0 = (ngc & 7) * 64;
            uint32_t so = (uint32_t)((ch + 1) & 1) * 2 * TILE_BYTES;
            fill_async(smb + so, Abase + ngc * 64, KV, tid);
            fill_async(smb + so + TILE_BYTES, Hbase + (size_t)k * Cc * Vv + i0, Vv, tid);
            CP_COMMIT();
            CP_WAIT1();
        } else {
            CP_WAIT0();
        }
        __syncthreads();
        uint32_t st = smb + (uint32_t)(ch & 1) * 2 * TILE_BYTES;
        mma_chunk(st + awoff, st + bwoff, acc);
        if (gc == 7)  acc_scale(acc, wks[0] / wks[1]);
        if (gc == 15) acc_scale(acc, wks[1] / wks[2]);
        __syncthreads();
    }
    float fs = ((ks == 0) ? wks[1] : wks[2]) * ascal;
    int g = lane >> 2, c = lane & 3;
    __half* part = g_aggp + (size_t)ks * BT * Vv * Cc;
#pragma unroll
    for (int mt = 0; mt < 4; mt++) {
#pragma unroll
        for (int nt = 0; nt < 8; nt++) {
            int row = wm * 64 + mt * 16 + g;
            int col = wn * 64 + nt * 8 + 2 * c;
            uint32_t* d0 = (uint32_t*)(part + ((size_t)bt * Vv + j0 + row) * Cc + col);
            uint32_t* d1 = (uint32_t*)(part + ((size_t)bt * Vv + j0 + row + 8) * Cc + col);
            *d0 = pack2(acc[mt][nt][0] * fs, acc[mt][nt][1] * fs);
            *d1 = pack2(acc[mt][nt][2] * fs, acc[mt][nt][3] * fs);
        }
    }
}

// z = (aggp0+aggp1) @ xproj_w[l]: M=BT*V, N=256, K=128 (2 K64 chunks).
__device__ __forceinline__ void fill_aggA(uint32_t* As, int m0, int ch, int tid) {
    const __half* p0 = g_aggp + (size_t)m0 * Cc + ch * 64;
    const __half* p1 = p0 + (size_t)BT * Vv * Cc;
#pragma unroll
    for (int q = 0; q < 8; q++) {
        int idx = q * 128 + tid;
        int r = idx >> 3;
        int s = (idx & 7) << 3;
        const __half2* a0 = (const __half2*)(p0 + (size_t)r * Cc + s);
        const __half2* b0 = (const __half2*)(p1 + (size_t)r * Cc + s);
        uint4 u;
        uint32_t* up = (uint32_t*)&u;
#pragma unroll
        for (int e = 0; e < 4; e++) {
            float2 a = __half22float2(a0[e]);
            float2 b = __half22float2(b0[e]);
            up[e] = pack2(a.x + b.x, a.y + b.y);
        }
        *(uint4*)(As + r * PADW + (s >> 1)) = u;
    }
}

__global__ __launch_bounds__(128, 3) void k_zgemm_mma(int l) {
    extern __shared__ __align__(16) uint32_t smp[];
    uint32_t smb = smem_u32(smp);
    int tid = threadIdx.x;
    int wid = tid >> 5, lane = tid & 31;
    int wm = wid >> 1, wn = wid & 1;
    int m0 = blockIdx.x * 128;
    int n0 = blockIdx.y * 128;
    float acc[4][8][4];
    ACC_INIT(acc);
    uint32_t awoff = (uint32_t)(wm * 64 * PADH * 2) + lane_a(lane);
    uint32_t bwoff = TILE_BYTES + (uint32_t)(wn * 64 * PADH * 2) + lane_b(lane);
    const __half* Bbase = g_xwTt + (size_t)l * C2 * Cc + (size_t)n0 * Cc;

    fill_async(smb + TILE_BYTES, Bbase, Cc, tid);
    CP_COMMIT();
    fill_aggA(smp, m0, 0, tid);
    const int NCH = 2;
    for (int ch = 0; ch < NCH; ch++) {
        if (ch + 1 < NCH) {
            uint32_t so = (uint32_t)((ch + 1) & 1) * 2 * TILE_BYTES;
            fill_async(smb + so + TILE_BYTES, Bbase + (ch + 1) * 64, Cc, tid);
            CP_COMMIT();
            fill_aggA(smp + (size_t)((ch + 1) & 1) * 2 * TILE_WORDS, m0, ch + 1, tid);
            CP_WAIT1();
        } else {
            CP_WAIT0();
        }
        __syncthreads();
        uint32_t st = smb + (uint32_t)(ch & 1) * 2 * TILE_BYTES;
        mma_chunk(st + awoff, st + bwoff, acc);
        __syncthreads();
    }
    int g = lane >> 2, c = lane & 3;
#pragma unroll
    for (int mt = 0; mt < 4; mt++) {
#pragma unroll
        for (int nt = 0; nt < 8; nt++) {
            int row = wm * 64 + mt * 16 + g;
            int col = wn * 64 + nt * 8 + 2 * c;
            uint32_t* d0 = (uint32_t*)(g_z + (size_t)(m0 + row) * C2 + n0 + col);
            uint32_t* d1 = (uint32_t*)(g_z + (size_t)(m0 + row + 8) * C2 + n0 + col);
            *d0 = pack2(acc[mt][nt][0], acc[mt][nt][1]);
            *d1 = pack2(acc[mt][nt][2], acc[mt][nt][3]);
        }
    }
}

// GFS fc split-K: partial[ks][b][v][o] (fp16) over K64 chunks [ks*4, ks*4+4)
__global__ __launch_bounds__(128, 3) void k_gfs_mma(int sidx) {
    extern __shared__ __align__(16) uint32_t smp[];
    uint32_t smb = smem_u32(smp);
    int tid = threadIdx.x;
    int wid = tid >> 5, lane = tid & 31;
    int wm = wid >> 1, wn = wid & 1;
    int v0 = blockIdx.x * 128;
    int b = blockIdx.y;
    int ks = blockIdx.z;
    float acc[4][8][4];
    ACC_INIT(acc);
    uint32_t awoff = (uint32_t)(wm * 64 * PADH * 2) + lane_a(lane);
    uint32_t bwoff = TILE_BYTES + (uint32_t)(wn * 64 * PADH * 2) + lane_b(lane);
    const __half* fw = g_fwt + (size_t)sidx * Cc * KTC;

    auto asrc = [&](int gch) -> const __half* {
        int t = gch >> 1, coff = (gch & 1) * 64;
        return g_ht + ((size_t)(b * TPAD + BETA + t) * Vv + v0) * Cc + coff;
    };
    int g0 = ks * 4;
    fill_async(smb, asrc(g0), Cc, tid);
    fill_async(smb + TILE_BYTES, fw + g0 * 64, KTC, tid);
    CP_COMMIT();
    const int NCH = 4;
    for (int ch = 0; ch < NCH; ch++) {
        if (ch + 1 < NCH) {
            int nc = g0 + ch + 1;
            uint32_t so = (uint32_t)((ch + 1) & 1) * 2 * TILE_BYTES;
            fill_async(smb + so, asrc(nc), Cc, tid);
            fill_async(smb + so + TILE_BYTES, fw + nc * 64, KTC, tid);
            CP_COMMIT();
            CP_WAIT1();
        } else {
            CP_WAIT0();
        }
        __syncthreads();
        uint32_t st = smb + (uint32_t)(ch & 1) * 2 * TILE_BYTES;
        mma_chunk(st + awoff, st + bwoff, acc);
        __syncthreads();
    }
    int g = lane >> 2, c = lane & 3;
    __half* part = g_spart + ((size_t)ks * Bb + b) * Vv * Cc;
#pragma unroll
    for (int mt = 0; mt < 4; mt++) {
#pragma unroll
        for (int nt = 0; nt < 8; nt++) {
            int row = wm * 64 + mt * 16 + g;
            int col = wn * 64 + nt * 8 + 2 * c;
            uint32_t* d0 = (uint32_t*)(part + (size_t)(v0 + row) * Cc + col);
            uint32_t* d1 = (uint32_t*)(part + (size_t)(v0 + row + 8) * Cc + col);
            *d0 = pack2(acc[mt][nt][0], acc[mt][nt][1]);
            *d1 = pack2(acc[mt][nt][2], acc[mt][nt][3]);
        }
    }
}

// head: g[b][p][v] = gb[p] + sum_o gw[p][o]*skipT[b][v][o] (8 K64 chunks)
__global__ __launch_bounds__(128, 3) void k_headg_mma(const float* __restrict__ gb) {
    extern __shared__ __align__(16) uint32_t smp[];
    uint32_t smb = smem_u32(smp);
    int tid = threadIdx.x;
    int wid = tid >> 5, lane = tid & 31;
    int wm = wid >> 1, wn = wid & 1;
    int p0 = blockIdx.x * 128;
    int b = blockIdx.y >> 2;
    int n0 = (blockIdx.y & 3) * 128;
    float acc[4][8][4];
    ACC_INIT(acc);
    uint32_t awoff = (uint32_t)(wm * 64 * PADH * 2) + lane_a(lane);
    uint32_t bwoff = TILE_BYTES + (uint32_t)(wn * 64 * PADH * 2) + lane_b(lane);
    const __half* Abase = g_gwt + (size_t)p0 * 512;
    const __half* Bbase = g_skipTt + ((size_t)b * Vv + n0) * 512;

    fill_async(smb, Abase, 512, tid);
    fill_async(smb + TILE_BYTES, Bbase, 512, tid);
    CP_COMMIT();
    const int NCH = 8;
    for (int ch = 0; ch < NCH; ch++) {
        if (ch + 1 < NCH) {
            uint32_t so = (uint32_t)((ch + 1) & 1) * 2 * TILE_BYTES;
            fill_async(smb + so, Abase + (ch + 1) * 64, 512, tid);
            fill_async(smb + so + TILE_BYTES, Bbase + (ch + 1) * 64, 512, tid);
            CP_COMMIT();
            CP_WAIT1();
        } else {
            CP_WAIT0();
        }
        __syncthreads();
        uint32_t st = smb + (uint32_t)(ch & 1) * 2 * TILE_BYTES;
        mma_chunk(st + awoff, st + bwoff, acc);
        __syncthreads();
    }
    int g = lane >> 2, c = lane & 3;
#pragma unroll
    for (int mt = 0; mt < 4; mt++) {
#pragma unroll
        for (int nt = 0; nt < 8; nt++) {
            int row = wm * 64 + mt * 16 + g;
            int col = wn * 64 + nt * 8 + 2 * c;
            float bi0 = gb[p0 + row], bi1 = gb[p0 + row + 8];
            uint32_t* d0 = (uint32_t*)(g_g + ((size_t)b * 1024 + p0 + row) * Vv + n0 + col);
            uint32_t* d1 = (uint32_t*)(g_g + ((size_t)b * 1024 + p0 + row + 8) * Vv + n0 + col);
            *d0 = pack2(acc[mt][nt][0] + bi0, acc[mt][nt][1] + bi0);
            *d1 = pack2(acc[mt][nt][2] + bi1, acc[mt][nt][3] + bi1);
        }
    }
}

// ---- fused add + LayerNorm + GLU -> h (fp16), z read as fp16 ----
__global__ __launch_bounds__(256) void k_lnglu(int l, const float* __restrict__ lng,
                                               const float* __restrict__ lnb) {
    int w = threadIdx.x >> 5, lane = threadIdx.x & 31;
    int row = blockIdx.x * 8 + w;
    int bt = row >> 9, v = row & 511;
    int b = bt / Tt, t = bt % Tt;
    const __half* zr = g_z + (size_t)row * C2;
    const float* sp = g_sep + ((size_t)l * Vv + v) * C2;
    const float* tp = g_tep + ((size_t)l * BT + bt) * C2;
    float val[8];
    float sum = 0.f;
#pragma unroll
    for (int q = 0; q < 8; q++) {
        int c2 = q * 32 + lane;
        val[q] = __half2float(zr[c2]) + sp[c2] + tp[c2];
        sum += val[q];
    }
#pragma unroll
    for (int o = 16; o; o >>= 1) sum += __shfl_xor_sync(0xffffffffu, sum, o);
    float mean = sum * (1.f / 256.f);
    float s2 = 0.f;
#pragma unroll
    for (int q = 0; q < 8; q++) { float df = val[q] - mean; s2 += df * df; }
#pragma unroll
    for (int o = 16; o; o >>= 1) s2 += __shfl_xor_sync(0xffffffffu, s2, o);
    float rstd = rsqrtf(s2 * (1.f / 256.f) + 1e-5f);
    float y[8];
#pragma unroll
    for (int q = 0; q < 8; q++) {
        int c2 = q * 32 + lane;
        y[q] = (val[q] - mean) * rstd * lng[l * C2 + c2] + lnb[l * C2 + c2];
    }
    size_t slab = (size_t)(b * TPAD + BETA + t);
    __half* hp = g_ht + (slab * Vv + v) * Cc;
#pragma unroll
    for (int q = 0; q < 4; q++)
        hp[q * 32 + lane] = __float2half_rn(y[q] * sigm(y[q + 4]));
}

// ---- GFS GLU (fused fp16 split-K reduce + bias; coalesced weights) ----
__global__ __launch_bounds__(128) void k_gfs_glu(int slot, const float* __restrict__ gb,
                                                 const float* __restrict__ fb) {
    int b = blockIdx.x >> 6;
    int v0 = (blockIdx.x & 63) * 8;
    __shared__ float s8[8][128];
    int o = threadIdx.x;
    float fbias = fb[o];
#pragma unroll
    for (int vi = 0; vi < 8; vi++) {
        float acc = fbias;
#pragma unroll
        for (int ks = 0; ks < KSPL; ks++)
            acc += __half2float(
                g_spart[(((size_t)ks * Bb + b) * Vv + v0 + vi) * Cc + o]);
        s8[vi][o] = acc;
    }
    __syncthreads();
    float al[8], ar[8];
    float bl = gb[o], br = gb[o + 128];
#pragma unroll
    for (int vi = 0; vi < 8; vi++) { al[vi] = bl; ar[vi] = br; }
    const float* wT = g_gluwT + (size_t)slot * Cc * C2;
    for (int c = 0; c < 128; c++) {
        float a  = wT[(size_t)c * C2 + o];
        float bw = wT[(size_t)c * C2 + 128 + o];
#pragma unroll
        for (int vi = 0; vi < 8; vi++) {
            float sv = s8[vi][c];
            al[vi] += a * sv;
            ar[vi] += bw * sv;
        }
    }
#pragma unroll
    for (int vi = 0; vi < 8; vi++)
        g_skipTt[((size_t)b * Vv + v0 + vi) * 512 + slot * 128 + o] =
            __float2half_rn(al[vi] * sigm(ar[vi]));
}

// ---- output head (split q), g read as fp16 ----
__global__ __launch_bounds__(512) void k_out_part(const float* __restrict__ ow) {
    __shared__ float ws[PP * 128];
    int b = blockIdx.x;
    int qs = blockIdx.y;
    int v = threadIdx.x;
    for (int i = v; i < PP * 128; i += 512) {
        int r = i >> 7, qq = i & 127;
        ws[i] = ow[r * 512 + qs * 128 + qq];
    }
    __syncthreads();
    float acc[PP];
#pragma unroll
    for (int r = 0; r < PP; r++) acc[r] = 0.f;
    const __half* gB = g_g + (size_t)b * 1024 * Vv;
    for (int qq = 0; qq < 128; qq++) {
        int q = qs * 128 + qq;
        float gl = __half2float(gB[(size_t)q * Vv + v]);
        float gr = __half2float(gB[(size_t)(512 + q) * Vv + v]);
        float gate = gl * sigm(gr);
#pragma unroll
        for (int r = 0; r < PP; r++) acc[r] += ws[r * 128 + qq] * gate;
    }
#pragma unroll
    for (int r = 0; r < PP; r++)
        g_opart[(((size_t)qs * Bb + b) * PP + r) * Vv + v] = acc[r];
}

__global__ void k_out_red(const float* __restrict__ ob, float* __restrict__ out) {
    int idx = blockIdx.x * blockDim.x + threadIdx.x;
    if (idx >= Bb * PP * Vv) return;
    int r = (idx / Vv) % PP;
    float s = ob[r];
#pragma unroll
    for (int qs = 0; qs < QSPL; qs++)
        s += g_opart[(size_t)qs * Bb * PP * Vv + idx];
    out[idx] = s;
}

// ---------------- orchestration ----------------
extern "C" void kernel_launch(void* const* d_in, const int* in_sizes, int n_in,
                              void* d_out, int out_size) {
    const float* x          = (const float*)d_in[0];
    const float* sape       = (const float*)d_in[1];
    const float* tape       = (const float*)d_in[2];
    const float* srpe       = (const float*)d_in[3];
    const float* trpe       = (const float*)d_in[4];
    const float* range_mask = (const float*)d_in[7];
    const float* input_w    = (const float*)d_in[8];
    const float* input_b    = (const float*)d_in[9];
    const float* fs0_fc_w   = (const float*)d_in[10];
    const float* fs0_fc_b   = (const float*)d_in[11];
    const float* fs0_glu_w  = (const float*)d_in[12];
    const float* fs0_glu_b  = (const float*)d_in[13];
    const float* mus        = (const float*)d_in[14];
    const float* isgs       = (const float*)d_in[15];
    const float* xproj_w    = (const float*)d_in[16];
    const float* xproj_b    = (const float*)d_in[17];
    const float* seproj_w   = (const float*)d_in[18];
    const float* teproj_w   = (const float*)d_in[19];
    const float* ln_g       = (const float*)d_in[20];
    const float* ln_b       = (const float*)d_in[21];
    const float* fs_fc_w    = (const float*)d_in[22];
    const float* fs_fc_b    = (const float*)d_in[23];
    const float* fs_glu_w   = (const float*)d_in[24];
    const float* fs_glu_b   = (const float*)d_in[25];
    const float* glu_w      = (const float*)d_in[26];
    const float* glu_b      = (const float*)d_in[27];
    const float* out_w      = (const float*)d_in[28];
    const float* out_b      = (const float*)d_in[29];
    float* out = (float*)d_out;

    cudaFuncSetAttribute(k_agg_mma,   cudaFuncAttributeMaxDynamicSharedMemorySize, SMEM_PIPE);
    cudaFuncSetAttribute(k_zgemm_mma, cudaFuncAttributeMaxDynamicSharedMemorySize, SMEM_PIPE);
    cudaFuncSetAttribute(k_gfs_mma,   cudaFuncAttributeMaxDynamicSharedMemorySize, SMEM_PIPE);
    cudaFuncSetAttribute(k_headg_mma, cudaFuncAttributeMaxDynamicSharedMemorySize, SMEM_PIPE);

    // slots 1..3 = prerequisites for agg(0); slot 4 = k_agg_mma(0) (profiled)
    k_input<<<(Bb * TPAD * Vv * Cc) / 256, 256>>>(x, input_w, input_b);
    k_transp<<<dim3(4, 16, Bb * TPAD), dim3(32, 8)>>>(0);
    k_buildE<<<LL * Vv * TSZ, 512>>>(sape, srpe, trpe, range_mask, mus, isgs);
    k_agg_mma<<<dim3(4, BT, ASPL), 128, SMEM_PIPE>>>(0, tape, mus, isgs);

    // remaining setup
    {
        int n = LL * C2 * Cc + 4 * Cc * KTC + 1024 * 512 + 4 * Cc * C2;
        k_cvtW<<<(n + 255) / 256, 256>>>(xproj_w, fs0_fc_w, fs_fc_w, glu_w,
                                         fs0_glu_w, fs_glu_w);
    }
    {
        int n = LL * Vv * C2 + LL * BT * C2;
        k_septep<<<(n + 255) / 256, 256>>>(sape, tape, seproj_w, teproj_w, xproj_b);
    }

    // skip slot 0 (uses pre-layer h; must precede lnglu(0))
    k_gfs_mma<<<dim3(4, Bb, KSPL), 128, SMEM_PIPE>>>(0);
    k_gfs_glu<<<Bb * 64, 128>>>(0, fs0_glu_b, fs0_fc_b);

    for (int l = 0; l < LL; l++) {
        if (l > 0) k_agg_mma<<<dim3(4, BT, ASPL), 128, SMEM_PIPE>>>(l, tape, mus, isgs);
        k_zgemm_mma<<<dim3(BT * Vv / 128, 2), 128, SMEM_PIPE>>>(l);
        k_lnglu<<<BT * Vv / 8, 256>>>(l, ln_g, ln_b);
        if (l < LL - 1)
            k_transp<<<dim3(4, 16, BT), dim3(32, 8)>>>(1);
        k_gfs_mma<<<dim3(4, Bb, KSPL), 128, SMEM_PIPE>>>(l + 1);
        k_gfs_glu<<<Bb * 64, 128>>>(l + 1, fs_glu_b + l * 2 * Cc, fs_fc_b + l * Cc);
    }

    // head
    k_headg_mma<<<dim3(8, 32), 128, SMEM_PIPE>>>(glu_b);
    k_out_part<<<dim3(Bb, QSPL), 512>>>(out_w);
    k_out_red<<<(Bb * PP * Vv + 255) / 256, 256>>>(out_b, out);
}